// round 15
// baseline (speedup 1.0000x reference)
#include <cuda_runtime.h>
#include <cuda_bf16.h>
#include <math.h>
#include <stdint.h>

// Problem constants
#define NB    4
#define NSEQ  1568
#define CDIM  1024
#define NH    16
#define HD    64
#define M_TOT (NB*NSEQ)          // 6272
#define QKV_OUT (3*CDIM)         // 3072
#define NKT   ((NSEQ+63)/64)     // 25 key tiles
#define NQT   ((NSEQ+127)/128)   // 13 query tiles

// Scratch (device globals — no allocation allowed)
__device__ float g_q[NB*NH*NSEQ*HD];
__device__ float g_k[NB*NH*NSEQ*HD];
__device__ float g_v[NB*NH*NSEQ*HD];

// Precomputed bf16 hi/lo operand arrays
__device__ uint16_t g_xh[M_TOT*CDIM],    g_xl[M_TOT*CDIM];
__device__ uint16_t g_wqh[QKV_OUT*CDIM], g_wql[QKV_OUT*CDIM];
__device__ uint16_t g_wph[CDIM*CDIM],    g_wpl[CDIM*CDIM];
__device__ uint16_t g_qh[NB*NH*NSEQ*HD], g_ql[NB*NH*NSEQ*HD];
__device__ uint16_t g_kh[NB*NH*NSEQ*HD], g_kl[NB*NH*NSEQ*HD];
__device__ uint16_t g_vh[NB*NH*NSEQ*HD], g_vl[NB*NH*NSEQ*HD];
__device__ uint16_t g_oh[M_TOT*CDIM],    g_ol[M_TOT*CDIM];

// ===========================================================================
// Warp-MMA helpers (compute_103-safe: mma.sync + ldmatrix, sm_80 features)
// ===========================================================================
__device__ __forceinline__ uint32_t smem_u32(const void* p) {
    uint32_t a;
    asm("{ .reg .u64 t; cvta.to.shared.u64 t, %1; cvt.u32.u64 %0, t; }"
        : "=r"(a) : "l"(p));
    return a;
}

#define LDMX4(r0, r1, r2, r3, addr) \
    asm volatile("ldmatrix.sync.aligned.m8n8.x4.shared.b16 {%0,%1,%2,%3}, [%4];" \
        : "=r"(r0), "=r"(r1), "=r"(r2), "=r"(r3) : "r"(addr))

#define LDMX4T(r0, r1, r2, r3, addr) \
    asm volatile("ldmatrix.sync.aligned.m8n8.x4.trans.shared.b16 {%0,%1,%2,%3}, [%4];" \
        : "=r"(r0), "=r"(r1), "=r"(r2), "=r"(r3) : "r"(addr))

#define MMA16816(d, a, b0, b1) \
    asm volatile("mma.sync.aligned.m16n8k16.row.col.f32.bf16.bf16.f32 " \
        "{%0,%1,%2,%3}, {%4,%5,%6,%7}, {%8,%9}, {%0,%1,%2,%3};" \
        : "+f"((d)[0]), "+f"((d)[1]), "+f"((d)[2]), "+f"((d)[3]) \
        : "r"((a)[0]), "r"((a)[1]), "r"((a)[2]), "r"((a)[3]), "r"(b0), "r"(b1))

// convert float4 -> 4 bf16 hi (uint2) + 4 bf16 lo (uint2)
__device__ __forceinline__ void cvt4_hl(float4 f, uint2& hi, uint2& lo) {
    float xs[4] = {f.x, f.y, f.z, f.w};
    uint32_t h[2], l[2];
    #pragma unroll
    for (int i = 0; i < 2; i++) {
        float a = xs[2*i], b = xs[2*i+1];
        __nv_bfloat16 ha = __float2bfloat16_rn(a);
        __nv_bfloat16 hb = __float2bfloat16_rn(b);
        float ra = a - __bfloat162float(ha);
        float rb = b - __bfloat162float(hb);
        __nv_bfloat16 la = __float2bfloat16_rn(ra);
        __nv_bfloat16 lb = __float2bfloat16_rn(rb);
        h[i] = (uint32_t)__bfloat16_as_ushort(ha) | ((uint32_t)__bfloat16_as_ushort(hb) << 16);
        l[i] = (uint32_t)__bfloat16_as_ushort(la) | ((uint32_t)__bfloat16_as_ushort(lb) << 16);
    }
    hi = make_uint2(h[0], h[1]);
    lo = make_uint2(l[0], l[1]);
}

__device__ __forceinline__ void pack2_hl(float a, float b, uint32_t& hi, uint32_t& lo) {
    __nv_bfloat16 ha = __float2bfloat16_rn(a);
    __nv_bfloat16 hb = __float2bfloat16_rn(b);
    __nv_bfloat16 la = __float2bfloat16_rn(a - __bfloat162float(ha));
    __nv_bfloat16 lb = __float2bfloat16_rn(b - __bfloat162float(hb));
    hi = (uint32_t)__bfloat16_as_ushort(ha) | ((uint32_t)__bfloat16_as_ushort(hb) << 16);
    lo = (uint32_t)__bfloat16_as_ushort(la) | ((uint32_t)__bfloat16_as_ushort(lb) << 16);
}

// ===========================================================================
// hi/lo precompute kernels. SEL: 0=x 1=Wqkv 2=Wproj 3=g_q 4=g_k 5=g_v
// ===========================================================================
template<int SEL>
__global__ __launch_bounds__(256) void cvt_hl(const float* __restrict__ src, int n)
{
    const int i = (blockIdx.x * 256 + threadIdx.x) * 4;
    if (i >= n) return;
    const float* s = src;
    uint16_t *hi, *lo;
    if      (SEL == 0) { hi = g_xh;  lo = g_xl;  }
    else if (SEL == 1) { hi = g_wqh; lo = g_wql; }
    else if (SEL == 2) { hi = g_wph; lo = g_wpl; }
    else if (SEL == 3) { s = g_q; hi = g_qh; lo = g_ql; }
    else if (SEL == 4) { s = g_k; hi = g_kh; lo = g_kl; }
    else               { s = g_v; hi = g_vh; lo = g_vl; }
    float4 f = *(const float4*)(s + i);
    uint2 h, l;
    cvt4_hl(f, h, l);
    *(uint2*)(hi + i) = h;
    *(uint2*)(lo + i) = l;
}

// ===========================================================================
// bf16 3-term-split GEMM via mma.sync, operands pre-split in gmem:
//   out[m,o] = sum_k A[m,k] * W[o,k]
//   EPI==0: A = x (g_xh/g_xl), B = Wqkv; scatter into g_q/g_k/g_v (f32)
//   EPI==1: A = attention O (g_oh/g_ol), B = Wproj; add bias, write out
// ===========================================================================
#define ASTR 24
#define NCH  (CDIM / 16)   // 64 chunks

template<int EPI>
__global__ __launch_bounds__(256, 2)
void gemm_mma(const float* __restrict__ bias, float* __restrict__ out)
{
    __shared__ __align__(16) uint16_t smA[2][2][128 * ASTR];  // [stage][hi/lo]
    __shared__ __align__(16) uint16_t smB[2][2][128 * ASTR];

    const int t    = threadIdx.x;
    const int lane = t & 31;
    const int w    = t >> 5;
    const int warpM = w >> 2;       // 0..1
    const int warpN = w & 3;        // 0..3
    const int m0 = blockIdx.y * 128;
    const int o0 = blockIdx.x * 128;

    const uint16_t* Ah_g = (EPI == 0) ? g_xh  : g_oh;
    const uint16_t* Al_g = (EPI == 0) ? g_xl  : g_ol;
    const uint16_t* Bh_g = (EPI == 0) ? g_wqh : g_wph;
    const uint16_t* Bl_g = (EPI == 0) ? g_wql : g_wpl;

    const int lrow = t >> 1;          // 0..127
    const int lco  = (t & 1) * 8;     // 0 or 8
    const uint16_t* Aph = Ah_g + (size_t)(m0 + lrow) * CDIM + lco;
    const uint16_t* Apl = Al_g + (size_t)(m0 + lrow) * CDIM + lco;
    const uint16_t* Bph = Bh_g + (size_t)(o0 + lrow) * CDIM + lco;
    const uint16_t* Bpl = Bl_g + (size_t)(o0 + lrow) * CDIM + lco;

    const int aR = warpM * 64;
    const uint32_t aFragOff = (uint32_t)(((lane & 15)) * ASTR + (lane >> 4) * 8);
    const uint32_t bRow  = (uint32_t)((lane & 7) + ((lane >> 4) << 3));
    const uint32_t bKoff = (uint32_t)(((lane >> 3) & 1) * 8);
    const int bN = warpN * 32;

    float acc[4][4][4];
    #pragma unroll
    for (int i = 0; i < 4; i++)
        #pragma unroll
        for (int j = 0; j < 4; j++)
            #pragma unroll
            for (int r = 0; r < 4; r++) acc[i][j][r] = 0.f;

    // prefetch chunk 0 (8 bf16 = one uint4 per tile per precision)
    uint4 pah = *(const uint4*)Aph;
    uint4 pal = *(const uint4*)Apl;
    uint4 pbh = *(const uint4*)Bph;
    uint4 pbl = *(const uint4*)Bpl;

    #pragma unroll 1
    for (int kc = 0; kc < NCH; kc++) {
        const int buf = kc & 1;
        *(uint4*)&smA[buf][0][lrow * ASTR + lco] = pah;
        *(uint4*)&smA[buf][1][lrow * ASTR + lco] = pal;
        *(uint4*)&smB[buf][0][lrow * ASTR + lco] = pbh;
        *(uint4*)&smB[buf][1][lrow * ASTR + lco] = pbl;
        __syncthreads();

        if (kc + 1 < NCH) {
            const int off = (kc + 1) * 16;
            pah = *(const uint4*)(Aph + off);
            pal = *(const uint4*)(Apl + off);
            pbh = *(const uint4*)(Bph + off);
            pbl = *(const uint4*)(Bpl + off);
        }

        // compute: 3 terms (Ah*Bh, Ah*Bl, Al*Bh)
        #pragma unroll
        for (int term = 0; term < 3; term++) {
            const uint16_t* Ab = smA[buf][term == 2 ? 1 : 0];
            const uint16_t* Bb = smB[buf][term == 1 ? 1 : 0];

            uint32_t af[4][4];
            #pragma unroll
            for (int mt = 0; mt < 4; mt++) {
                uint32_t addr = smem_u32(Ab + (aR + mt * 16) * ASTR) + aFragOff * 2;
                LDMX4(af[mt][0], af[mt][1], af[mt][2], af[mt][3], addr);
            }
            uint32_t bf[4][2];
            #pragma unroll
            for (int ntp = 0; ntp < 2; ntp++) {
                uint32_t addr = smem_u32(Bb + (bN + ntp * 16 + bRow) * ASTR + bKoff);
                LDMX4(bf[2*ntp][0], bf[2*ntp][1], bf[2*ntp+1][0], bf[2*ntp+1][1], addr);
            }
            #pragma unroll
            for (int mt = 0; mt < 4; mt++)
                #pragma unroll
                for (int nt = 0; nt < 4; nt++)
                    MMA16816(acc[mt][nt], af[mt], bf[nt][0], bf[nt][1]);
        }
        __syncthreads();
    }

    // Epilogue
    const int lr = lane >> 2;
    const int lc = (lane & 3) * 2;
    #pragma unroll
    for (int mt = 0; mt < 4; mt++) {
        #pragma unroll
        for (int nt = 0; nt < 4; nt++) {
            const int o = o0 + warpN * 32 + nt * 8 + lc;
            #pragma unroll
            for (int half = 0; half < 2; half++) {
                const int m = m0 + warpM * 64 + mt * 16 + lr + half * 8;
                float2 v = make_float2(acc[mt][nt][half * 2], acc[mt][nt][half * 2 + 1]);
                if (EPI == 0) {
                    const int s  = o >> 10;
                    const int h  = (o >> 6) & 15;
                    const int d0 = o & 63;
                    const int b  = m / NSEQ;
                    const int n  = m - b * NSEQ;
                    float* dst = (s == 0 ? g_q : s == 1 ? g_k : g_v)
                                 + (((size_t)(b * NH + h)) * NSEQ + n) * HD + d0;
                    *(float2*)dst = v;
                } else {
                    v.x += bias[o];
                    v.y += bias[o + 1];
                    *(float2*)(out + (size_t)m * CDIM + o) = v;
                }
            }
        }
    }
}

// ---------------------------------------------------------------------------
// RoPE (unchanged, matches reference's interleaved-pair indexing exactly)
// ---------------------------------------------------------------------------
__global__ void rope_kernel()
{
    const int total = 2 * NB * NH * NSEQ * 30;
    int i = blockIdx.x * blockDim.x + threadIdx.x;
    if (i >= total) return;

    const int p30  = i % 30;
    int rest       = i / 30;
    const int bhn  = rest % (NB * NH * NSEQ);
    const int tsel = rest / (NB * NH * NSEQ);

    const int n  = bhn % NSEQ;
    const int bh = bhn / NSEQ;

    const int a = p30 / 10;
    const int p = p30 % 10;

    const int rem = n % 196;
    float pos;
    if (a == 0)      pos = (float)(n / 196);
    else if (a == 1) pos = (float)(rem / 14);
    else             pos = (float)(rem % 14);

    const int d0 = a * 20 + 2 * p;
    const int f0 = (2 * p) % 10;
    const int f1 = (2 * p + 1) % 10;
    const float LOG1E4 = 9.210340371976184f;
    const float w0 = expf(-(float)f0 * 0.1f * LOG1E4);
    const float w1 = expf(-(float)f1 * 0.1f * LOG1E4);

    float s0, c0, s1, c1;
    sincosf(pos * w0, &s0, &c0);
    sincosf(pos * w1, &s1, &c1);

    float* buf = tsel ? g_k : g_q;
    const size_t base = ((size_t)bh * NSEQ + n) * HD;
    const float x0 = buf[base + d0];
    const float x1 = buf[base + d0 + 1];
    buf[base + d0]     = x0 * c0 - x1 * s0;
    buf[base + d0 + 1] = x1 * c1 + x0 * s1;
}

// ===========================================================================
// Flash attention via mma.sync, bf16 3-term split on BOTH QK^T and PV.
//   Q/K/V pre-split in gmem (g_qh/... after RoPE); O written as hi/lo bf16.
//   CTA = 128 q-rows x one (b,h). 8 warps x 16 q-rows. KT=64 key tiles.
// ===========================================================================
#define QSTR 72
#define ATTN_SMEM ((2*128 + 4*64) * QSTR * 2)   // 73728 B

__global__ __launch_bounds__(256, 1) void attn_mma()
{
    extern __shared__ uint16_t smu[];
    uint16_t* Qh = smu;                   // [128][QSTR]
    uint16_t* Ql = Qh + 128 * QSTR;
    uint16_t* Kh = Ql + 128 * QSTR;       // [64][QSTR]
    uint16_t* Kl = Kh + 64 * QSTR;
    uint16_t* Vh = Kl + 64 * QSTR;
    uint16_t* Vl = Vh + 64 * QSTR;

    const int t    = threadIdx.x;
    const int lane = t & 31;
    const int wid  = t >> 5;
    const int bh   = blockIdx.y;
    const int q0   = blockIdx.x * 128;

    const size_t bhoff = (size_t)bh * NSEQ * HD;
    const uint16_t* Qph = g_qh + bhoff;
    const uint16_t* Qpl = g_ql + bhoff;
    const uint16_t* Kph = g_kh + bhoff;
    const uint16_t* Kpl = g_kl + bhoff;
    const uint16_t* Vph = g_vh + bhoff;
    const uint16_t* Vpl = g_vl + bhoff;

    const uint2 z2 = make_uint2(0u, 0u);

    // ---- load Q tile (pre-split hi/lo): 128 rows x 64 cols = 2048 uint2 ----
    #pragma unroll
    for (int it = 0; it < 8; it++) {
        const int f   = it * 256 + t;      // uint2 index over 128x64
        const int row = f >> 4;            // 0..127
        const int c   = (f & 15) * 4;      // 0..60
        const int gq  = q0 + row;
        uint2 h = z2, l = z2;
        if (gq < NSEQ) {
            h = *(const uint2*)(Qph + (size_t)gq * HD + c);
            l = *(const uint2*)(Qpl + (size_t)gq * HD + c);
        }
        *(uint2*)&Qh[row * QSTR + c] = h;
        *(uint2*)&Ql[row * QSTR + c] = l;
    }
    __syncthreads();

    // ---- hoist Q fragments (4 k-chunks x 4 regs, hi+lo) ----
    uint32_t qh[4][4], ql[4][4];
    {
        const int aRow = wid * 16 + (lane & 15);
        const int aCol = (lane >> 4) * 8;
        #pragma unroll
        for (int kc = 0; kc < 4; kc++) {
            uint32_t ad = smem_u32(&Qh[aRow * QSTR + kc * 16 + aCol]);
            LDMX4(qh[kc][0], qh[kc][1], qh[kc][2], qh[kc][3], ad);
            ad = smem_u32(&Ql[aRow * QSTR + kc * 16 + aCol]);
            LDMX4(ql[kc][0], ql[kc][1], ql[kc][2], ql[kc][3], ad);
        }
    }

    float oacc[8][4];
    #pragma unroll
    for (int i = 0; i < 8; i++)
        #pragma unroll
        for (int j = 0; j < 4; j++) oacc[i][j] = 0.f;
    float m0v = -3.0e38f, m1v = -3.0e38f, l0 = 0.f, l1 = 0.f;

    const int bRow = (lane & 7) + ((lane >> 4) << 3);
    const int bK   = ((lane >> 3) & 1) * 8;
    const int vRow = (lane & 7) + (lane & 8);
    const int vCol = ((lane >> 4) << 3);

    #pragma unroll 1
    for (int kt = 0; kt < NKT; kt++) {
        const int k0 = kt * 64;
        __syncthreads();   // previous tile fully consumed
        // ---- load K,V tiles (pre-split hi/lo): 64 rows x 64 cols = 1024 uint2 each ----
        #pragma unroll
        for (int it = 0; it < 4; it++) {
            const int f   = it * 256 + t;  // uint2 index over 64x64
            const int row = f >> 4;        // 0..63
            const int c   = (f & 15) * 4;  // 0..60
            const int gk  = k0 + row;
            const bool ok = (gk < NSEQ);
            const size_t go = (size_t)gk * HD + c;
            *(uint2*)&Kh[row * QSTR + c] = ok ? *(const uint2*)(Kph + go) : z2;
            *(uint2*)&Kl[row * QSTR + c] = ok ? *(const uint2*)(Kpl + go) : z2;
            *(uint2*)&Vh[row * QSTR + c] = ok ? *(const uint2*)(Vph + go) : z2;
            *(uint2*)&Vl[row * QSTR + c] = ok ? *(const uint2*)(Vpl + go) : z2;
        }
        __syncthreads();

        // ---- S = Q K^T (3-term split) ----
        float s[8][4];
        #pragma unroll
        for (int i = 0; i < 8; i++)
            #pragma unroll
            for (int j = 0; j < 4; j++) s[i][j] = 0.f;

        #pragma unroll
        for (int np = 0; np < 4; np++) {
            #pragma unroll
            for (int kc = 0; kc < 4; kc++) {
                uint32_t kh0, kh1, kh2, kh3, kl0, kl1, kl2, kl3;
                uint32_t ad = smem_u32(&Kh[(np * 16 + bRow) * QSTR + kc * 16 + bK]);
                LDMX4(kh0, kh1, kh2, kh3, ad);
                ad = smem_u32(&Kl[(np * 16 + bRow) * QSTR + kc * 16 + bK]);
                LDMX4(kl0, kl1, kl2, kl3, ad);
                MMA16816(s[2*np],   qh[kc], kh0, kh1);
                MMA16816(s[2*np],   qh[kc], kl0, kl1);
                MMA16816(s[2*np],   ql[kc], kh0, kh1);
                MMA16816(s[2*np+1], qh[kc], kh2, kh3);
                MMA16816(s[2*np+1], qh[kc], kl2, kl3);
                MMA16816(s[2*np+1], ql[kc], kh2, kh3);
            }
        }

        // ---- online softmax ----
        const float scale = 0.125f;
        float rmax0 = -3.0e38f, rmax1 = -3.0e38f;
        const bool last = (kt == NKT - 1);
        #pragma unroll
        for (int nt = 0; nt < 8; nt++) {
            #pragma unroll
            for (int j = 0; j < 2; j++) {
                s[nt][j]     *= scale;
                s[nt][j + 2] *= scale;
                if (last) {
                    const int col = k0 + nt * 8 + (lane & 3) * 2 + j;
                    if (col >= NSEQ) { s[nt][j] = -1.0e30f; s[nt][j + 2] = -1.0e30f; }
                }
                rmax0 = fmaxf(rmax0, s[nt][j]);
                rmax1 = fmaxf(rmax1, s[nt][j + 2]);
            }
        }
        rmax0 = fmaxf(rmax0, __shfl_xor_sync(0xffffffffu, rmax0, 1));
        rmax0 = fmaxf(rmax0, __shfl_xor_sync(0xffffffffu, rmax0, 2));
        rmax1 = fmaxf(rmax1, __shfl_xor_sync(0xffffffffu, rmax1, 1));
        rmax1 = fmaxf(rmax1, __shfl_xor_sync(0xffffffffu, rmax1, 2));

        const float mn0 = fmaxf(m0v, rmax0);
        const float mn1 = fmaxf(m1v, rmax1);
        const float al0 = __expf(m0v - mn0);
        const float al1 = __expf(m1v - mn1);
        m0v = mn0; m1v = mn1;

        float rs0 = 0.f, rs1 = 0.f;
        #pragma unroll
        for (int nt = 0; nt < 8; nt++) {
            #pragma unroll
            for (int j = 0; j < 2; j++) {
                s[nt][j]     = __expf(s[nt][j]     - mn0);
                s[nt][j + 2] = __expf(s[nt][j + 2] - mn1);
                rs0 += s[nt][j];
                rs1 += s[nt][j + 2];
            }
        }
        rs0 += __shfl_xor_sync(0xffffffffu, rs0, 1);
        rs0 += __shfl_xor_sync(0xffffffffu, rs0, 2);
        rs1 += __shfl_xor_sync(0xffffffffu, rs1, 1);
        rs1 += __shfl_xor_sync(0xffffffffu, rs1, 2);
        l0 = l0 * al0 + rs0;
        l1 = l1 * al1 + rs1;

        #pragma unroll
        for (int nt = 0; nt < 8; nt++) {
            oacc[nt][0] *= al0; oacc[nt][1] *= al0;
            oacc[nt][2] *= al1; oacc[nt][3] *= al1;
        }

        // ---- P -> bf16 hi/lo A-fragments (register-only) ----
        uint32_t ph[4][4], pl[4][4];
        #pragma unroll
        for (int kc = 0; kc < 4; kc++) {
            pack2_hl(s[2*kc][0],   s[2*kc][1],   ph[kc][0], pl[kc][0]);
            pack2_hl(s[2*kc][2],   s[2*kc][3],   ph[kc][1], pl[kc][1]);
            pack2_hl(s[2*kc+1][0], s[2*kc+1][1], ph[kc][2], pl[kc][2]);
            pack2_hl(s[2*kc+1][2], s[2*kc+1][3], ph[kc][3], pl[kc][3]);
        }

        // ---- O += P V (3-term split), V via ldmatrix.trans ----
        #pragma unroll
        for (int dp = 0; dp < 4; dp++) {
            #pragma unroll
            for (int kc = 0; kc < 4; kc++) {
                uint32_t vh0, vh1, vh2, vh3, vl0, vl1, vl2, vl3;
                uint32_t ad = smem_u32(&Vh[(kc * 16 + vRow) * QSTR + dp * 16 + vCol]);
                LDMX4T(vh0, vh1, vh2, vh3, ad);
                ad = smem_u32(&Vl[(kc * 16 + vRow) * QSTR + dp * 16 + vCol]);
                LDMX4T(vl0, vl1, vl2, vl3, ad);
                MMA16816(oacc[2*dp],   ph[kc], vh0, vh1);
                MMA16816(oacc[2*dp],   ph[kc], vl0, vl1);
                MMA16816(oacc[2*dp],   pl[kc], vh0, vh1);
                MMA16816(oacc[2*dp+1], ph[kc], vh2, vh3);
                MMA16816(oacc[2*dp+1], ph[kc], vl2, vl3);
                MMA16816(oacc[2*dp+1], pl[kc], vh2, vh3);
            }
        }
    }

    // ---- epilogue: normalize + store hi/lo bf16 to g_oh/g_ol [B,N,C] ----
    const float inv0 = 1.0f / l0;
    const float inv1 = 1.0f / l1;
    const int b = bh >> 4;
    const int h = bh & 15;
    const int r0g = q0 + wid * 16 + (lane >> 2);
    #pragma unroll
    for (int nt = 0; nt < 8; nt++) {
        const int d = h * HD + nt * 8 + (lane & 3) * 2;
        uint32_t hh, ll;
        if (r0g < NSEQ) {
            pack2_hl(oacc[nt][0] * inv0, oacc[nt][1] * inv0, hh, ll);
            const size_t off = ((size_t)b * NSEQ + r0g) * CDIM + d;
            *(uint32_t*)(g_oh + off) = hh;
            *(uint32_t*)(g_ol + off) = ll;
        }
        if (r0g + 8 < NSEQ) {
            pack2_hl(oacc[nt][2] * inv1, oacc[nt][3] * inv1, hh, ll);
            const size_t off = ((size_t)b * NSEQ + r0g + 8) * CDIM + d;
            *(uint32_t*)(g_oh + off) = hh;
            *(uint32_t*)(g_ol + off) = ll;
        }
    }
}

// ---------------------------------------------------------------------------
extern "C" void kernel_launch(void* const* d_in, const int* in_sizes, int n_in,
                              void* d_out, int out_size)
{
    const float* x     = (const float*)d_in[0];
    const float* Wqkv  = (const float*)d_in[1];
    const float* Wproj = (const float*)d_in[2];
    const float* bproj = (const float*)d_in[3];
    float* out = (float*)d_out;

    cudaFuncSetAttribute(attn_mma,
                         cudaFuncAttributeMaxDynamicSharedMemorySize, ATTN_SMEM);

    // 0) Pre-split x, Wqkv, Wproj into bf16 hi/lo
    cvt_hl<0><<<(M_TOT * CDIM) / 1024, 256>>>(x, M_TOT * CDIM);
    cvt_hl<1><<<(QKV_OUT * CDIM) / 1024, 256>>>(Wqkv, QKV_OUT * CDIM);
    cvt_hl<2><<<(CDIM * CDIM) / 1024, 256>>>(Wproj, CDIM * CDIM);

    // 1) QKV projection (mma.sync bf16 3-term) -> g_q/g_k/g_v (f32)
    gemm_mma<0><<<dim3(QKV_OUT / 128, M_TOT / 128), 256>>>(nullptr, nullptr);

    // 2) RoPE in place on q, k (f32)
    const int rope_total = 2 * NB * NH * NSEQ * 30;
    rope_kernel<<<(rope_total + 255) / 256, 256>>>();

    // 3) Pre-split q, k, v into bf16 hi/lo
    const int qkv_n = NB * NH * NSEQ * HD;
    cvt_hl<3><<<qkv_n / 1024, 256>>>(nullptr, qkv_n);
    cvt_hl<4><<<qkv_n / 1024, 256>>>(nullptr, qkv_n);
    cvt_hl<5><<<qkv_n / 1024, 256>>>(nullptr, qkv_n);

    // 4) Attention (mma.sync, split precision) -> g_oh/g_ol (bf16 hi/lo)
    attn_mma<<<dim3(NQT, NB * NH), 256, ATTN_SMEM>>>();

    // 5) Output projection + bias -> d_out (mma.sync bf16 3-term)
    gemm_mma<1><<<dim3(CDIM / 128, M_TOT / 128), 256>>>(bproj, out);
}